// round 4
// baseline (speedup 1.0000x reference)
#include <cuda_runtime.h>
#include <cuda_bf16.h>

// Holt-Winters additive triple smoothing, one thread per series row.
// series: [B, T] f32 row-major. shifts: [B] i32. season: [SLEN] f32.
// out[b, 0]   = series[b,0] + init_trend
// for t>=1:
//   sea        = season[(t - shift_b) mod SLEN]
//   smooth_new = alpha*(y_t - sea) + (1-alpha)*(smooth + trend)
//   trend_new  = beta*(smooth_new - smooth) + (1-beta)*trend
//   out[b, t]  = smooth_new + trend_new + sea
// (gamma is unused by the reference: season is never updated.)

__device__ __forceinline__ float hw_step(float y, float sea,
                                         float& smooth, float& trend,
                                         float alpha, float oma,
                                         float beta, float omb)
{
    float sn = alpha * (y - sea) + oma * (smooth + trend);
    float tn = beta * (sn - smooth) + omb * trend;
    smooth = sn;
    trend  = tn;
    return sn + tn + sea;
}

__global__ __launch_bounds__(256)
void hw_kernel(const float* __restrict__ series,
               const int*   __restrict__ shifts,
               const float* __restrict__ alpha_p,
               const float* __restrict__ beta_p,
               const float* __restrict__ season_g,
               const float* __restrict__ init_trend_p,
               float* __restrict__ out,
               int B, int T, int slen)
{
    __shared__ float s_season[64];
    __shared__ float s_scal[3];

    if (threadIdx.x < slen) s_season[threadIdx.x] = season_g[threadIdx.x];
    if (threadIdx.x == 0) {
        s_scal[0] = *alpha_p;
        s_scal[1] = *beta_p;
        s_scal[2] = *init_trend_p;
    }
    __syncthreads();

    int row = blockIdx.x * blockDim.x + threadIdx.x;
    if (row >= B) return;

    const float alpha = s_scal[0];
    const float beta  = s_scal[1];
    const float oma   = 1.0f - alpha;
    const float omb   = 1.0f - beta;

    int shift = shifts[row];
    // season index for t=1: ((1 - shift) mod slen + slen) mod slen
    int idx = (1 - shift) % slen;
    if (idx < 0) idx += slen;

    const float4* __restrict__ src = (const float4*)(series + (size_t)row * T);
    float4* __restrict__ dst = (float4*)(out + (size_t)row * T);
    const int nchunk = T >> 2;  // T = 512 -> 128 chunks

    float4 cur = src[0];
    float4 nxt = src[1];

    float smooth = cur.x;
    float trend  = s_scal[2];

    // chunk 0: t=0 special (no season term), t=1..3 normal steps
    {
        float4 r;
        r.x = smooth + trend;

        float sea;
        sea = s_season[idx]; idx = (idx + 1 == slen) ? 0 : idx + 1;
        r.y = hw_step(cur.y, sea, smooth, trend, alpha, oma, beta, omb);
        sea = s_season[idx]; idx = (idx + 1 == slen) ? 0 : idx + 1;
        r.z = hw_step(cur.z, sea, smooth, trend, alpha, oma, beta, omb);
        sea = s_season[idx]; idx = (idx + 1 == slen) ? 0 : idx + 1;
        r.w = hw_step(cur.w, sea, smooth, trend, alpha, oma, beta, omb);

        dst[0] = r;
    }

    #pragma unroll 4
    for (int c = 1; c < nchunk; ++c) {
        cur = nxt;
        // prefetch next chunk (clamped on the last iteration; value unused)
        int cn = (c + 1 < nchunk) ? (c + 1) : c;
        nxt = src[cn];

        float4 r;
        float sea;
        sea = s_season[idx]; idx = (idx + 1 == slen) ? 0 : idx + 1;
        r.x = hw_step(cur.x, sea, smooth, trend, alpha, oma, beta, omb);
        sea = s_season[idx]; idx = (idx + 1 == slen) ? 0 : idx + 1;
        r.y = hw_step(cur.y, sea, smooth, trend, alpha, oma, beta, omb);
        sea = s_season[idx]; idx = (idx + 1 == slen) ? 0 : idx + 1;
        r.z = hw_step(cur.z, sea, smooth, trend, alpha, oma, beta, omb);
        sea = s_season[idx]; idx = (idx + 1 == slen) ? 0 : idx + 1;
        r.w = hw_step(cur.w, sea, smooth, trend, alpha, oma, beta, omb);

        dst[c] = r;
    }
}

extern "C" void kernel_launch(void* const* d_in, const int* in_sizes, int n_in,
                              void* d_out, int out_size)
{
    // metadata order:
    // 0: series       f32 [B*T]
    // 1: series_shifts i32 [B]
    // 2: alpha        f32 [1]
    // 3: beta         f32 [1]
    // 4: gamma        f32 [1]   (unused by reference)
    // 5: init_season  f32 [SLEN]
    // 6: init_trend   f32 [1]
    // 7: n_preds      (0 -> full output)
    const float* series     = (const float*)d_in[0];
    const int*   shifts     = (const int*)  d_in[1];
    const float* alpha_p    = (const float*)d_in[2];
    const float* beta_p     = (const float*)d_in[3];
    const float* season     = (const float*)d_in[5];
    const float* init_trend = (const float*)d_in[6];
    float* out = (float*)d_out;

    int B    = in_sizes[1];
    int T    = in_sizes[0] / B;
    int slen = in_sizes[5];

    int threads = 256;
    int blocks  = (B + threads - 1) / threads;
    hw_kernel<<<blocks, threads>>>(series, shifts, alpha_p, beta_p, season,
                                   init_trend, out, B, T, slen);
}

// round 5
// speedup vs baseline: 1.2135x; 1.2135x over previous
#include <cuda_runtime.h>
#include <cuda_bf16.h>

// Holt-Winters additive triple smoothing.
// Reference recurrence (gamma unused; season never updated):
//   out[b,0]   = series[b,0] + init_trend
//   sea_t      = init_season[(t - shift_b) mod SLEN]
//   smooth'    = alpha*(y_t - sea_t) + (1-alpha)*(smooth + trend)
//   trend'     = beta*(smooth' - smooth) + (1-beta)*trend
//   out[b,t]   = smooth' + trend' + sea_t
//
// R5 strategy: smem-transpose tiling. One thread still owns one row's serial
// recurrence, but all global loads/stores go through staging tiles so each
// warp touches full 128-byte lines (R4 profile showed l1tex wavefronts
// binding at L1=64% / DRAM=31% due to 2KB-stride float4 lanes).

constexpr int ROWS   = 64;   // rows per block == threads per block
constexpr int THREADS = 64;
constexpr int C      = 32;   // time-steps per chunk
constexpr int CH4    = C / 4;         // float4s per row per chunk (8)
constexpr int SIN    = 33;   // in-tile row stride (floats): conflict-free scalar LDS
constexpr int SOUT   = 36;   // out-tile row stride (floats): 16B-aligned vector ops

__device__ __forceinline__ float hw_step(float y, float sea,
                                         float& smooth, float& trend,
                                         float alpha, float oma,
                                         float beta, float omb)
{
    float sn = alpha * (y - sea) + oma * (smooth + trend);
    float tn = beta * (sn - smooth) + omb * trend;
    smooth = sn;
    trend  = tn;
    return sn + tn + sea;
}

__global__ __launch_bounds__(THREADS)
void hw_kernel(const float* __restrict__ series,
               const int*   __restrict__ shifts,
               const float* __restrict__ alpha_p,
               const float* __restrict__ beta_p,
               const float* __restrict__ season_g,
               const float* __restrict__ init_trend_p,
               float* __restrict__ out,
               int B, int T, int slen)
{
    __shared__ float s_in [ROWS * SIN];   // 8448 B
    __shared__ float s_out[ROWS * SOUT];  // 9216 B
    __shared__ float s_season[16];

    const int t = threadIdx.x;
    if (t < slen) s_season[t] = season_g[t];
    // scalars: uniform broadcast loads (L2/const path), cheap
    const float alpha      = *alpha_p;
    const float beta       = *beta_p;
    const float init_trend = *init_trend_p;
    const float oma = 1.0f - alpha;
    const float omb = 1.0f - beta;

    const int row0 = blockIdx.x * ROWS;          // first global row of block
    const int myrow = row0 + t;

    int shift = shifts[myrow];
    int idx = (1 - shift) % slen;                // season index for t=1
    if (idx < 0) idx += slen;

    const int t4 = T >> 2;                       // float4s per row (128)
    const float4* __restrict__ srcv = (const float4*)series;
    float4*       __restrict__ dstv = (float4*)out;

    float smooth = 0.0f, trend = 0.0f;           // set at ch==0
    const int nchunk = T / C;                    // 16

    __syncthreads();                             // season tile visible

    for (int ch = 0; ch < nchunk; ++ch) {
        // ---- load phase: coalesced 128B lines -> s_in -------------------
        // q = k*THREADS + t ; row = q/8 ; c4 = q%8
        // 8 consecutive threads cover one row's 32 floats (one full line).
        #pragma unroll
        for (int k = 0; k < (ROWS * CH4) / THREADS; ++k) {
            int q   = k * THREADS + t;
            int r   = q >> 3;
            int c4  = q & 7;
            float4 v = srcv[(size_t)(row0 + r) * t4 + ch * CH4 + c4];
            float* p = s_in + r * SIN + c4 * 4;
            p[0] = v.x; p[1] = v.y; p[2] = v.z; p[3] = v.w;
        }
        __syncthreads();   // S1: tile ready; prior chunk's s_out reads done

        // ---- compute phase: thread t owns row t (private smem region) ---
        {
            const float* rin  = s_in  + t * SIN;
            float4*      rout = (float4*)(s_out + t * SOUT);
            int g0 = 0;
            if (ch == 0) {
                float y0 = rin[0];
                smooth = y0;
                trend  = init_trend;
                float o0 = smooth + trend;
                float sea;
                sea = s_season[idx]; idx = (idx + 1 == slen) ? 0 : idx + 1;
                float o1 = hw_step(rin[1], sea, smooth, trend, alpha, oma, beta, omb);
                sea = s_season[idx]; idx = (idx + 1 == slen) ? 0 : idx + 1;
                float o2 = hw_step(rin[2], sea, smooth, trend, alpha, oma, beta, omb);
                sea = s_season[idx]; idx = (idx + 1 == slen) ? 0 : idx + 1;
                float o3 = hw_step(rin[3], sea, smooth, trend, alpha, oma, beta, omb);
                rout[0] = make_float4(o0, o1, o2, o3);
                g0 = 1;
            }
            #pragma unroll
            for (int g = 0; g < CH4; ++g) {
                if (g < g0) continue;
                float sea;
                sea = s_season[idx]; idx = (idx + 1 == slen) ? 0 : idx + 1;
                float o0 = hw_step(rin[g * 4 + 0], sea, smooth, trend, alpha, oma, beta, omb);
                sea = s_season[idx]; idx = (idx + 1 == slen) ? 0 : idx + 1;
                float o1 = hw_step(rin[g * 4 + 1], sea, smooth, trend, alpha, oma, beta, omb);
                sea = s_season[idx]; idx = (idx + 1 == slen) ? 0 : idx + 1;
                float o2 = hw_step(rin[g * 4 + 2], sea, smooth, trend, alpha, oma, beta, omb);
                sea = s_season[idx]; idx = (idx + 1 == slen) ? 0 : idx + 1;
                float o3 = hw_step(rin[g * 4 + 3], sea, smooth, trend, alpha, oma, beta, omb);
                rout[g] = make_float4(o0, o1, o2, o3);
            }
        }
        __syncthreads();   // S2: results visible; s_in reads done (safe to
                           //     overwrite s_in next iteration)

        // ---- store phase: coalesced 128B lines from s_out ---------------
        #pragma unroll
        for (int k = 0; k < (ROWS * CH4) / THREADS; ++k) {
            int q   = k * THREADS + t;
            int r   = q >> 3;
            int c4  = q & 7;
            const float4* p = (const float4*)(s_out + r * SOUT) + c4;
            dstv[(size_t)(row0 + r) * t4 + ch * CH4 + c4] = *p;
        }
        // no barrier here: next compute writes s_out only after S1, which
        // orders all threads' store-phase reads.
    }
}

extern "C" void kernel_launch(void* const* d_in, const int* in_sizes, int n_in,
                              void* d_out, int out_size)
{
    // 0: series f32 [B*T]   1: shifts i32 [B]   2: alpha   3: beta
    // 4: gamma (unused)     5: init_season [SLEN]   6: init_trend   7: n_preds
    const float* series     = (const float*)d_in[0];
    const int*   shifts     = (const int*)  d_in[1];
    const float* alpha_p    = (const float*)d_in[2];
    const float* beta_p     = (const float*)d_in[3];
    const float* season     = (const float*)d_in[5];
    const float* init_trend = (const float*)d_in[6];
    float* out = (float*)d_out;

    int B    = in_sizes[1];
    int T    = in_sizes[0] / B;      // 512
    int slen = in_sizes[5];          // 12

    int blocks = B / ROWS;           // 1024
    hw_kernel<<<blocks, THREADS>>>(series, shifts, alpha_p, beta_p, season,
                                   init_trend, out, B, T, slen);
}

// round 7
// speedup vs baseline: 1.5906x; 1.3108x over previous
#include <cuda_runtime.h>
#include <cuda_bf16.h>
#include <cstdint>

// Holt-Winters additive triple smoothing (gamma unused; season static):
//   out[b,0] = series[b,0] + init_trend
//   sea_t    = init_season[(t - shift_b) mod SLEN]
//   smooth'  = alpha*(y_t - sea_t) + (1-alpha)*(smooth + trend)
//   trend'   = beta*(smooth' - smooth) + (1-beta)*trend
//   out[b,t] = smooth' + trend' + sea_t
//
// R6: R5's coalesced smem-transpose tiling + DOUBLE-BUFFERED cp.async
// prefetch so DRAM latency overlaps the serial compute phase (R5 profile:
// DRAM 38%, phases serialized, occupancy capped at ~14 warps/SM).

constexpr int ROWS    = 64;   // rows per block == threads
constexpr int THREADS = 64;
constexpr int C       = 32;   // time-steps per chunk
constexpr int CH4     = C / 4;
constexpr int SIN     = 33;   // in-tile stride: conflict-free scalar LDS + cp.async4
constexpr int SOUT    = 36;   // out-tile stride: 16B-aligned, conflict-free vec ops

__device__ __forceinline__ uint32_t smem_u32(const void* p) {
    return (uint32_t)__cvta_generic_to_shared(p);
}
__device__ __forceinline__ void cp_async4(uint32_t dst, const void* src) {
    asm volatile("cp.async.ca.shared.global [%0], [%1], 4;\n"
                 :: "r"(dst), "l"(src) : "memory");
}
__device__ __forceinline__ void cp_commit() {
    asm volatile("cp.async.commit_group;\n" ::: "memory");
}
template <int N>
__device__ __forceinline__ void cp_wait() {
    asm volatile("cp.async.wait_group %0;\n" :: "n"(N) : "memory");
}

__device__ __forceinline__ float hw_step(float y, float sea,
                                         float& smooth, float& trend,
                                         float alpha, float oma,
                                         float beta, float omb)
{
    float sn = alpha * (y - sea) + oma * (smooth + trend);
    float tn = beta * (sn - smooth) + omb * trend;
    smooth = sn;
    trend  = tn;
    return sn + tn + sea;
}

__global__ __launch_bounds__(THREADS)
void hw_kernel(const float* __restrict__ series,
               const int*   __restrict__ shifts,
               const float* __restrict__ alpha_p,
               const float* __restrict__ beta_p,
               const float* __restrict__ season_g,
               const float* __restrict__ init_trend_p,
               float* __restrict__ out,
               int B, int T, int slen)
{
    __shared__ float s_in [2][ROWS * SIN];  // 2 x 8448 B
    __shared__ float s_out[ROWS * SOUT];    // 9216 B
    __shared__ float s_season[16];

    const int t = threadIdx.x;
    if (t < slen) s_season[t] = season_g[t];

    const float alpha      = *alpha_p;
    const float beta       = *beta_p;
    const float init_trend = *init_trend_p;
    const float oma = 1.0f - alpha;
    const float omb = 1.0f - beta;

    const int row0 = blockIdx.x * ROWS;
    int shift = shifts[row0 + t];
    int idx = (1 - shift) % slen;            // season index for t=1
    if (idx < 0) idx += slen;

    const int nchunk = T / C;                // 16
    const int t4 = T >> 2;
    float4* __restrict__ dstv = (float4*)out;

    float smooth = 0.0f, trend = 0.0f;

    // ---- prologue: prefetch chunk 0 into buf 0 --------------------------
    // mapping: q = k*THREADS + t ; r = q>>5 ; c = q&31
    // -> each warp-instruction covers one row's 32 consecutive floats (128B).
    {
        #pragma unroll
        for (int k = 0; k < (ROWS * C) / THREADS; ++k) {
            int q = k * THREADS + t;
            int r = q >> 5;
            int c = q & 31;
            cp_async4(smem_u32(&s_in[0][r * SIN + c]),
                      series + (size_t)(row0 + r) * T + c);
        }
        cp_commit();
    }

    for (int ch = 0; ch < nchunk; ++ch) {
        const int buf = ch & 1;

        cp_wait<0>();        // chunk ch's data has landed (this thread's ops)
        __syncthreads();     // S1: all threads' data visible; also retires all
                             // reads of s_in[buf^1] (compute ch-1 ended at its
                             // S2, which precedes this barrier)

        // ---- issue prefetch of chunk ch+1 into the other buffer ---------
        if (ch + 1 < nchunk) {
            #pragma unroll
            for (int k = 0; k < (ROWS * C) / THREADS; ++k) {
                int q = k * THREADS + t;
                int r = q >> 5;
                int c = q & 31;
                cp_async4(smem_u32(&s_in[buf ^ 1][r * SIN + c]),
                          series + (size_t)(row0 + r) * T + (ch + 1) * C + c);
            }
        }
        cp_commit();         // flies during compute + store below

        // ---- compute: thread t owns row t (private smem region) ---------
        {
            const float* rin  = s_in[buf] + t * SIN;
            float4*      rout = (float4*)(s_out + t * SOUT);
            int g0 = 0;
            if (ch == 0) {
                smooth = rin[0];
                trend  = init_trend;
                float o0 = smooth + trend;
                float sea;
                sea = s_season[idx]; idx = (idx + 1 == slen) ? 0 : idx + 1;
                float o1 = hw_step(rin[1], sea, smooth, trend, alpha, oma, beta, omb);
                sea = s_season[idx]; idx = (idx + 1 == slen) ? 0 : idx + 1;
                float o2 = hw_step(rin[2], sea, smooth, trend, alpha, oma, beta, omb);
                sea = s_season[idx]; idx = (idx + 1 == slen) ? 0 : idx + 1;
                float o3 = hw_step(rin[3], sea, smooth, trend, alpha, oma, beta, omb);
                rout[0] = make_float4(o0, o1, o2, o3);
                g0 = 1;
            }
            #pragma unroll
            for (int g = 0; g < CH4; ++g) {
                if (g < g0) continue;
                float sea;
                sea = s_season[idx]; idx = (idx + 1 == slen) ? 0 : idx + 1;
                float o0 = hw_step(rin[g * 4 + 0], sea, smooth, trend, alpha, oma, beta, omb);
                sea = s_season[idx]; idx = (idx + 1 == slen) ? 0 : idx + 1;
                float o1 = hw_step(rin[g * 4 + 1], sea, smooth, trend, alpha, oma, beta, omb);
                sea = s_season[idx]; idx = (idx + 1 == slen) ? 0 : idx + 1;
                float o2 = hw_step(rin[g * 4 + 2], sea, smooth, trend, alpha, oma, beta, omb);
                sea = s_season[idx]; idx = (idx + 1 == slen) ? 0 : idx + 1;
                float o3 = hw_step(rin[g * 4 + 3], sea, smooth, trend, alpha, oma, beta, omb);
                rout[g] = make_float4(o0, o1, o2, o3);
            }
        }
        __syncthreads();     // S2: s_out complete

        // ---- store: coalesced 128B lines from s_out ---------------------
        // quarter-warp = 8 lanes = one row's 8 float4 (contiguous in smem
        // and in gmem) -> conflict-free LDS.128, fully-coalesced STG.128.
        #pragma unroll
        for (int k = 0; k < (ROWS * CH4) / THREADS; ++k) {
            int q  = k * THREADS + t;
            int r  = q >> 3;
            int c4 = q & 7;
            const float4* p = (const float4*)(s_out + r * SOUT) + c4;
            dstv[(size_t)(row0 + r) * t4 + ch * CH4 + c4] = *p;
        }
        // no barrier: next iteration's S1 orders these s_out reads before
        // the next compute overwrites s_out.
    }
}

extern "C" void kernel_launch(void* const* d_in, const int* in_sizes, int n_in,
                              void* d_out, int out_size)
{
    // 0: series f32 [B*T]   1: shifts i32 [B]   2: alpha   3: beta
    // 4: gamma (unused)     5: init_season [SLEN]   6: init_trend   7: n_preds
    const float* series     = (const float*)d_in[0];
    const int*   shifts     = (const int*)  d_in[1];
    const float* alpha_p    = (const float*)d_in[2];
    const float* beta_p     = (const float*)d_in[3];
    const float* season     = (const float*)d_in[5];
    const float* init_trend = (const float*)d_in[6];
    float* out = (float*)d_out;

    int B    = in_sizes[1];
    int T    = in_sizes[0] / B;      // 512
    int slen = in_sizes[5];          // 12

    int blocks = B / ROWS;           // 1024
    hw_kernel<<<blocks, THREADS>>>(series, shifts, alpha_p, beta_p, season,
                                   init_trend, out, B, T, slen);
}

// round 8
// speedup vs baseline: 1.8762x; 1.1796x over previous
#include <cuda_runtime.h>
#include <cuda_bf16.h>
#include <cstdint>

// Holt-Winters additive triple smoothing (gamma unused; season static):
//   out[b,0] = series[b,0] + init_trend
//   sea_t    = init_season[(t - shift_b) mod SLEN]
//   smooth'  = alpha*(y_t - sea_t) + (1-alpha)*(smooth + trend)
//   trend'   = beta*(smooth' - smooth) + (1-beta)*trend
//   out[b,t] = smooth' + trend' + sea_t
//
// R8: single-warp blocks, 2 rows per thread (2x ILP on the serial chain),
// cp.async 16B + LDS.128 staging (smem stride 36 -> conflict-free), warp-
// level sync only, 1024 blocks for ~3% wave imbalance.

constexpr int ROWS    = 64;   // rows per block
constexpr int THREADS = 32;   // one warp per block
constexpr int C       = 32;   // time-steps per chunk
constexpr int CH4     = C / 4;        // 8 float4 per row-chunk
constexpr int S       = 36;   // smem row stride (floats): 16B-aligned, bank-tiling

__device__ __forceinline__ uint32_t smem_u32(const void* p) {
    return (uint32_t)__cvta_generic_to_shared(p);
}
__device__ __forceinline__ void cp_async16(uint32_t dst, const void* src) {
    asm volatile("cp.async.cg.shared.global [%0], [%1], 16;\n"
                 :: "r"(dst), "l"(src) : "memory");
}
__device__ __forceinline__ void cp_commit() {
    asm volatile("cp.async.commit_group;\n" ::: "memory");
}
template <int N>
__device__ __forceinline__ void cp_wait() {
    asm volatile("cp.async.wait_group %0;\n" :: "n"(N) : "memory");
}

__device__ __forceinline__ float hw_step(float y, float sea,
                                         float& smooth, float& trend,
                                         float alpha, float oma,
                                         float beta, float omb)
{
    float sn = alpha * (y - sea) + oma * (smooth + trend);
    float tn = beta * (sn - smooth) + omb * trend;
    smooth = sn;
    trend  = tn;
    return sn + tn + sea;
}

__global__ __launch_bounds__(THREADS)
void hw_kernel(const float* __restrict__ series,
               const int*   __restrict__ shifts,
               const float* __restrict__ alpha_p,
               const float* __restrict__ beta_p,
               const float* __restrict__ season_g,
               const float* __restrict__ init_trend_p,
               float* __restrict__ out,
               int B, int T, int slen)
{
    __shared__ float s_in [2][ROWS * S];  // 2 x 9216 B
    __shared__ float s_out[ROWS * S];     //     9216 B
    __shared__ float s_season[16];

    const int lane = threadIdx.x;
    if (lane < slen) s_season[lane] = season_g[lane];

    const float alpha      = *alpha_p;
    const float beta       = *beta_p;
    const float init_trend = *init_trend_p;
    const float oma = 1.0f - alpha;
    const float omb = 1.0f - beta;

    const int row0 = blockIdx.x * ROWS;
    const int rowA = lane;          // this thread's first row (block-local)
    const int rowB = lane + 32;     // second row

    int shiftA = shifts[row0 + rowA];
    int shiftB = shifts[row0 + rowB];
    int idxA = (1 - shiftA) % slen; if (idxA < 0) idxA += slen;
    int idxB = (1 - shiftB) % slen; if (idxB < 0) idxB += slen;

    const int nchunk = T / C;       // 16
    const int t4 = T >> 2;
    float4* __restrict__ dstv = (float4*)out;

    float smoothA = 0.0f, trendA = 0.0f;
    float smoothB = 0.0f, trendB = 0.0f;

    __syncwarp();                   // season visible

    // ---- prologue: prefetch chunk 0 into buf 0 --------------------------
    // q = k*32 + lane ; r = q>>3 ; f4 = q&7 : 8 lanes cover one row's 128B.
    #pragma unroll
    for (int k = 0; k < (ROWS * CH4) / THREADS; ++k) {
        int q  = k * THREADS + lane;
        int r  = q >> 3;
        int f4 = q & 7;
        cp_async16(smem_u32(&s_in[0][r * S + f4 * 4]),
                   series + (size_t)(row0 + r) * T + f4 * 4);
    }
    cp_commit();

    for (int ch = 0; ch < nchunk; ++ch) {
        const int buf = ch & 1;

        cp_wait<0>();   // chunk ch landed (only its group is outstanding)
        __syncwarp();   // cross-lane visibility of the staged tile

        // ---- issue prefetch of chunk ch+1 into the other buffer ---------
        if (ch + 1 < nchunk) {
            const float* src = series + (size_t)(ch + 1) * C;
            #pragma unroll
            for (int k = 0; k < (ROWS * CH4) / THREADS; ++k) {
                int q  = k * THREADS + lane;
                int r  = q >> 3;
                int f4 = q & 7;
                cp_async16(smem_u32(&s_in[buf ^ 1][r * S + f4 * 4]),
                           src + (size_t)(row0 + r) * T + f4 * 4);
            }
        }
        cp_commit();    // flies during compute + store below

        // ---- compute: two independent rows per thread (2x ILP) ----------
        {
            const float4* rinA  = (const float4*)(s_in[buf] + rowA * S);
            const float4* rinB  = (const float4*)(s_in[buf] + rowB * S);
            float4*       routA = (float4*)(s_out + rowA * S);
            float4*       routB = (float4*)(s_out + rowB * S);

            int g0 = 0;
            if (ch == 0) {
                float4 a = rinA[0];
                float4 b = rinB[0];
                smoothA = a.x; trendA = init_trend;
                smoothB = b.x; trendB = init_trend;
                float4 oa, ob;
                oa.x = smoothA + trendA;
                ob.x = smoothB + trendB;
                float seaA, seaB;
                seaA = s_season[idxA]; idxA = (idxA + 1 == slen) ? 0 : idxA + 1;
                seaB = s_season[idxB]; idxB = (idxB + 1 == slen) ? 0 : idxB + 1;
                oa.y = hw_step(a.y, seaA, smoothA, trendA, alpha, oma, beta, omb);
                ob.y = hw_step(b.y, seaB, smoothB, trendB, alpha, oma, beta, omb);
                seaA = s_season[idxA]; idxA = (idxA + 1 == slen) ? 0 : idxA + 1;
                seaB = s_season[idxB]; idxB = (idxB + 1 == slen) ? 0 : idxB + 1;
                oa.z = hw_step(a.z, seaA, smoothA, trendA, alpha, oma, beta, omb);
                ob.z = hw_step(b.z, seaB, smoothB, trendB, alpha, oma, beta, omb);
                seaA = s_season[idxA]; idxA = (idxA + 1 == slen) ? 0 : idxA + 1;
                seaB = s_season[idxB]; idxB = (idxB + 1 == slen) ? 0 : idxB + 1;
                oa.w = hw_step(a.w, seaA, smoothA, trendA, alpha, oma, beta, omb);
                ob.w = hw_step(b.w, seaB, smoothB, trendB, alpha, oma, beta, omb);
                routA[0] = oa;
                routB[0] = ob;
                g0 = 1;
            }
            #pragma unroll
            for (int g = 0; g < CH4; ++g) {
                if (g < g0) continue;
                float4 a = rinA[g];
                float4 b = rinB[g];
                float4 oa, ob;
                float seaA, seaB;
                seaA = s_season[idxA]; idxA = (idxA + 1 == slen) ? 0 : idxA + 1;
                seaB = s_season[idxB]; idxB = (idxB + 1 == slen) ? 0 : idxB + 1;
                oa.x = hw_step(a.x, seaA, smoothA, trendA, alpha, oma, beta, omb);
                ob.x = hw_step(b.x, seaB, smoothB, trendB, alpha, oma, beta, omb);
                seaA = s_season[idxA]; idxA = (idxA + 1 == slen) ? 0 : idxA + 1;
                seaB = s_season[idxB]; idxB = (idxB + 1 == slen) ? 0 : idxB + 1;
                oa.y = hw_step(a.y, seaA, smoothA, trendA, alpha, oma, beta, omb);
                ob.y = hw_step(b.y, seaB, smoothB, trendB, alpha, oma, beta, omb);
                seaA = s_season[idxA]; idxA = (idxA + 1 == slen) ? 0 : idxA + 1;
                seaB = s_season[idxB]; idxB = (idxB + 1 == slen) ? 0 : idxB + 1;
                oa.z = hw_step(a.z, seaA, smoothA, trendA, alpha, oma, beta, omb);
                ob.z = hw_step(b.z, seaB, smoothB, trendB, alpha, oma, beta, omb);
                seaA = s_season[idxA]; idxA = (idxA + 1 == slen) ? 0 : idxA + 1;
                seaB = s_season[idxB]; idxB = (idxB + 1 == slen) ? 0 : idxB + 1;
                oa.w = hw_step(a.w, seaA, smoothA, trendA, alpha, oma, beta, omb);
                ob.w = hw_step(b.w, seaB, smoothB, trendB, alpha, oma, beta, omb);
                routA[g] = oa;
                routB[g] = ob;
            }
        }
        __syncwarp();   // s_out complete, visible across lanes

        // ---- store: quarter-warp = one row's 128B line ------------------
        #pragma unroll
        for (int k = 0; k < (ROWS * CH4) / THREADS; ++k) {
            int q  = k * THREADS + lane;
            int r  = q >> 3;
            int f4 = q & 7;
            const float4* p = (const float4*)(s_out + r * S) + f4;
            dstv[(size_t)(row0 + r) * t4 + ch * CH4 + f4] = *p;
        }
        // next iteration's __syncwarp (after cp_wait) orders these s_out
        // reads before the next compute overwrites s_out.
    }
}

extern "C" void kernel_launch(void* const* d_in, const int* in_sizes, int n_in,
                              void* d_out, int out_size)
{
    // 0: series f32 [B*T]   1: shifts i32 [B]   2: alpha   3: beta
    // 4: gamma (unused)     5: init_season [SLEN]   6: init_trend   7: n_preds
    const float* series     = (const float*)d_in[0];
    const int*   shifts     = (const int*)  d_in[1];
    const float* alpha_p    = (const float*)d_in[2];
    const float* beta_p     = (const float*)d_in[3];
    const float* season     = (const float*)d_in[5];
    const float* init_trend = (const float*)d_in[6];
    float* out = (float*)d_out;

    int B    = in_sizes[1];
    int T    = in_sizes[0] / B;      // 512
    int slen = in_sizes[5];          // 12

    int blocks = B / ROWS;           // 1024
    hw_kernel<<<blocks, THREADS>>>(series, shifts, alpha_p, beta_p, season,
                                   init_trend, out, B, T, slen);
}